// round 1
// baseline (speedup 1.0000x reference)
#include <cuda_runtime.h>
#include <cstdint>
#include <math.h>

#define B_   32
#define T_   1600
#define E_   1024
#define D_   1024
#define A_   512
#define C_   10
#define KW   201
#define FILTR 100

// output layout: ctx (B,E), w (B,T), h_new (B,A), c_new (B,A)
#define OUT_CTX 0
#define OUT_W   (B_*E_)
#define OUT_H   (OUT_W + B_*T_)
#define OUT_CN  (OUT_H + B_*A_)

// scratch (__device__ globals: no allocation allowed)
__device__ float g_Wt[E_*A_];     // W_enc transposed, k-major (E, A)
__device__ float g_feat[B_*C_];   // conv features
__device__ float g_sv[B_*A_];     // h_new + dec_proj + b_enc
__device__ float g_e[B_*T_];      // attention scores

static __device__ __forceinline__ float sigmf(float x){ return 1.0f/(1.0f+expf(-x)); }

static __device__ __forceinline__ unsigned smem_u32(const void* p){
    return (unsigned)__cvta_generic_to_shared(p);
}
static __device__ __forceinline__ void cp16(unsigned d, const void* s){
    asm volatile("cp.async.cg.shared.global [%0], [%1], 16;" :: "r"(d), "l"(s));
}
static __device__ __forceinline__ void cp4(unsigned d, const void* s){
    asm volatile("cp.async.ca.shared.global [%0], [%1], 4;" :: "r"(d), "l"(s));
}
static __device__ __forceinline__ unsigned long long fma2(unsigned long long a,
                                                          unsigned long long b,
                                                          unsigned long long c){
    unsigned long long d;
    asm("fma.rn.f32x2 %0, %1, %2, %3;" : "=l"(d) : "l"(a), "l"(b), "l"(c));
    return d;
}
static __device__ __forceinline__ unsigned long long dup2(float x){
    unsigned long long d;
    asm("mov.b64 %0, {%1, %1};" : "=l"(d) : "f"(x));
    return d;
}

// ---------------------------------------------------------------------------
// Kernel 0: transpose W_enc (A,E) -> g_Wt (E,A)
// ---------------------------------------------------------------------------
__global__ void transpose_kernel(const float* __restrict__ W){
    __shared__ float tile[32][33];
    int k0 = blockIdx.x*32, a0 = blockIdx.y*32;
    int tx = threadIdx.x, ty = threadIdx.y;   // block (32,8)
    #pragma unroll
    for (int j=0;j<4;j++)
        tile[ty+8*j][tx] = W[(size_t)(a0+ty+8*j)*E_ + k0 + tx];   // tile[a][k]
    __syncthreads();
    #pragma unroll
    for (int j=0;j<4;j++)
        g_Wt[(size_t)(k0+ty+8*j)*A_ + a0 + tx] = tile[tx][ty+8*j];
}

// ---------------------------------------------------------------------------
// Kernel 1: location conv + relu + global max-pool -> g_feat (B, C)
// grid (B, C), 256 threads
// ---------------------------------------------------------------------------
__global__ void conv_kernel(const float* __restrict__ ap, const float* __restrict__ cw){
    __shared__ float xp[T_ + 2*FILTR];   // zero-padded att_prev row
    __shared__ float wk[KW];
    __shared__ float red[256];
    int b = blockIdx.x, c = blockIdx.y, tid = threadIdx.x;
    for (int i=tid;i<T_+2*FILTR;i+=256){
        int t = i - FILTR;
        xp[i] = (t>=0 && t<T_) ? ap[b*T_+t] : 0.f;
    }
    for (int i=tid;i<KW;i+=256) wk[i] = cw[c*KW + i];
    __syncthreads();
    float m = 0.f;   // relu folds into max with 0 init
    for (int t=tid;t<T_;t+=256){
        float acc = 0.f;
        #pragma unroll 4
        for (int k=0;k<KW;k++) acc = fmaf(xp[t+k], wk[k], acc);
        m = fmaxf(m, acc);
    }
    red[tid]=m; __syncthreads();
    for (int s=128;s>0;s>>=1){ if (tid<s) red[tid]=fmaxf(red[tid],red[tid+s]); __syncthreads(); }
    if (tid==0) g_feat[b*C_+c] = red[0];
}

// ---------------------------------------------------------------------------
// Kernel 2: LSTM cell + dec_proj + sv = h_new + dec_proj + b_enc
// grid B, 512 threads (16 warps)
// ---------------------------------------------------------------------------
__global__ __launch_bounds__(512) void lstm_kernel(
    const float* __restrict__ dec_z, const float* __restrict__ att_h,
    const float* __restrict__ att_c, const float* __restrict__ b_enc,
    const float* __restrict__ W_dec, const float* __restrict__ W_ih,
    const float* __restrict__ W_hh, float* __restrict__ out)
{
    __shared__ float s_feat[16];
    __shared__ float s_h[A_];
    __shared__ float s_z[D_];
    __shared__ float s_g[4*A_];
    __shared__ float s_hn[A_];
    int b = blockIdx.x, tid = threadIdx.x;
    int lane = tid & 31, wp = tid >> 5;
    if (tid < C_) s_feat[tid] = g_feat[b*C_+tid];
    s_h[tid] = att_h[b*A_+tid];
    s_z[tid] = dec_z[b*D_+tid];
    s_z[tid+512] = dec_z[b*D_+tid+512];
    __syncthreads();
    // gates (4A rows, warp per row)
    for (int r = wp; r < 4*A_; r += 16){
        float acc = 0.f;
        const float* wr = &W_hh[(size_t)r*A_];
        for (int a=lane;a<A_;a+=32) acc = fmaf(s_h[a], wr[a], acc);
        if (lane < C_) acc = fmaf(s_feat[lane], W_ih[r*C_+lane], acc);
        #pragma unroll
        for (int o=16;o>0;o>>=1) acc += __shfl_xor_sync(0xffffffffu, acc, o);
        if (lane==0) s_g[r] = acc;
    }
    __syncthreads();
    {
        int a = tid;
        float ig=s_g[a], fg=s_g[A_+a], gg=s_g[2*A_+a], og=s_g[3*A_+a];
        float cn = sigmf(fg)*att_c[b*A_+a] + sigmf(ig)*tanhf(gg);
        float hn = sigmf(og)*tanhf(cn);
        out[OUT_H  + b*A_ + a] = hn;
        out[OUT_CN + b*A_ + a] = cn;
        s_hn[a] = hn;
    }
    __syncthreads();
    // dec_proj + sv
    for (int r = wp; r < A_; r += 16){
        float acc = 0.f;
        const float* wr = &W_dec[(size_t)r*D_];
        for (int d=lane;d<D_;d+=32) acc = fmaf(s_z[d], wr[d], acc);
        #pragma unroll
        for (int o=16;o>0;o>>=1) acc += __shfl_xor_sync(0xffffffffu, acc, o);
        if (lane==0) g_sv[b*A_+r] = acc + s_hn[r] + b_enc[r];
    }
}

// ---------------------------------------------------------------------------
// Kernel 3: fused score GEMM  e[b,t] = W_g . tanh(sv[b] + enc[b,t] @ Wt) + b_g
// BM=32, BN=512 (all A), BK=8, 256 threads, f32x2 FFMA2 accumulators,
// 2-stage cp.async pipeline. grid (T/32, B).
// ---------------------------------------------------------------------------
__global__ __launch_bounds__(256, 2) void score_kernel(
    const float* __restrict__ enc, const float* __restrict__ Wg,
    const float* __restrict__ bg)
{
    __shared__ __align__(16) float sW[2][8][512];
    __shared__ __align__(16) float sE[2][32][8];
    __shared__ float s_sv[512];
    __shared__ float s_wg[512];

    const int b  = blockIdx.y;
    const int t0 = blockIdx.x * 32;
    const int tid = threadIdx.x;
    const int tx = tid & 31, ty = tid >> 5;

    s_sv[tid]     = g_sv[b*A_ + tid];
    s_sv[tid+256] = g_sv[b*A_ + tid + 256];
    s_wg[tid]     = Wg[tid];
    s_wg[tid+256] = Wg[tid+256];

    const float* encb = enc + ((size_t)b*T_ + t0) * E_;
    const int erow = tid >> 3, ekk = tid & 7;

    auto issue = [&](int st, int kt){
        const int k0 = kt * 8;
        #pragma unroll
        for (int j=0;j<4;j++){
            int f  = j*256 + tid;        // float4 index within 8x512 tile
            int row = f >> 7;            // 0..7
            int c4  = (f & 127) << 2;    // float offset, multiple of 4
            cp16(smem_u32(&sW[st][row][c4]), &g_Wt[(size_t)(k0+row)*A_ + c4]);
        }
        cp4(smem_u32(&sE[st][erow][ekk]), &encb[(size_t)erow*E_ + k0 + ekk]);
        asm volatile("cp.async.commit_group;" ::: "memory");
    };

    unsigned long long acc[4][8];
    #pragma unroll
    for (int i=0;i<4;i++)
        #pragma unroll
        for (int p=0;p<8;p++) acc[i][p] = 0ull;

    issue(0, 0);
    const int NK = E_ / 8;   // 128

    #pragma unroll 1
    for (int kt=0; kt<NK; kt++){
        const int cur = kt & 1;
        if (kt + 1 < NK){
            issue(cur ^ 1, kt + 1);
            asm volatile("cp.async.wait_group 1;" ::: "memory");
        } else {
            asm volatile("cp.async.wait_group 0;" ::: "memory");
        }
        __syncthreads();
        #pragma unroll
        for (int k=0;k<8;k++){
            unsigned long long d0 = dup2(sE[cur][ty*4+0][k]);
            unsigned long long d1 = dup2(sE[cur][ty*4+1][k]);
            unsigned long long d2 = dup2(sE[cur][ty*4+2][k]);
            unsigned long long d3 = dup2(sE[cur][ty*4+3][k]);
            #pragma unroll
            for (int v=0; v<4; v++){
                const ulonglong2 wp = *reinterpret_cast<const ulonglong2*>(
                    &sW[cur][k][v*128 + tx*4]);
                acc[0][v*2+0] = fma2(d0, wp.x, acc[0][v*2+0]);
                acc[0][v*2+1] = fma2(d0, wp.y, acc[0][v*2+1]);
                acc[1][v*2+0] = fma2(d1, wp.x, acc[1][v*2+0]);
                acc[1][v*2+1] = fma2(d1, wp.y, acc[1][v*2+1]);
                acc[2][v*2+0] = fma2(d2, wp.x, acc[2][v*2+0]);
                acc[2][v*2+1] = fma2(d2, wp.y, acc[2][v*2+1]);
                acc[3][v*2+0] = fma2(d3, wp.x, acc[3][v*2+0]);
                acc[3][v*2+1] = fma2(d3, wp.y, acc[3][v*2+1]);
            }
        }
        __syncthreads();
    }

    // epilogue: + sv, tanh, * W_g, row-reduce
    const float bgv = bg[0];
    #pragma unroll
    for (int i=0;i<4;i++){
        float part = 0.f;
        #pragma unroll
        for (int v=0;v<4;v++){
            #pragma unroll
            for (int p=0;p<2;p++){
                int a = v*128 + tx*4 + p*2;
                float x0, x1;
                asm("mov.b64 {%0, %1}, %2;" : "=f"(x0), "=f"(x1) : "l"(acc[i][v*2+p]));
                x0 += s_sv[a];
                x1 += s_sv[a+1];
                part = fmaf(s_wg[a],   tanhf(x0), part);
                part = fmaf(s_wg[a+1], tanhf(x1), part);
            }
        }
        #pragma unroll
        for (int o=16;o>0;o>>=1) part += __shfl_xor_sync(0xffffffffu, part, o);
        if (tx==0) g_e[b*T_ + t0 + ty*4 + i] = part + bgv;
    }
}

// ---------------------------------------------------------------------------
// Kernel 4: masked scaled softmax -> out w section. grid B, 256 threads.
// ---------------------------------------------------------------------------
__global__ void softmax_kernel(const int* __restrict__ len, float* __restrict__ out){
    __shared__ float se[T_];
    __shared__ float red[256];
    int b = blockIdx.x, tid = threadIdx.x;
    int L = len[b];
    for (int t=tid;t<T_;t+=256) se[t] = g_e[b*T_+t];
    __syncthreads();
    float m = -3.4e38f;
    for (int t=tid;t<L;t+=256) m = fmaxf(m, se[t]);
    red[tid]=m; __syncthreads();
    for (int s=128;s>0;s>>=1){ if (tid<s) red[tid]=fmaxf(red[tid],red[tid+s]); __syncthreads(); }
    m = red[0];
    __syncthreads();
    float sum = 0.f;
    for (int t=tid;t<T_;t+=256){
        float v = (t<L) ? expf(2.0f*(se[t]-m)) : 0.f;
        se[t] = v;
        sum += v;
    }
    red[tid]=sum; __syncthreads();
    for (int s=128;s>0;s>>=1){ if (tid<s) red[tid]+=red[tid+s]; __syncthreads(); }
    float inv = 1.0f/red[0];
    for (int t=tid;t<T_;t+=256) out[OUT_W + b*T_ + t] = se[t]*inv;
}

// ---------------------------------------------------------------------------
// Kernel 5: ctx = w @ enc. grid (B, E/256), 256 threads.
// ---------------------------------------------------------------------------
__global__ void ctx_kernel(const float* __restrict__ enc, float* __restrict__ out){
    __shared__ float sw[T_];
    int b = blockIdx.x;
    int ec = blockIdx.y*256 + threadIdx.x;
    for (int t=threadIdx.x;t<T_;t+=256) sw[t] = out[OUT_W + b*T_ + t];
    __syncthreads();
    const float* eb = enc + (size_t)b*T_*E_ + ec;
    float a0=0.f, a1=0.f, a2=0.f, a3=0.f;
    #pragma unroll 1
    for (int t=0;t<T_;t+=4){
        a0 = fmaf(sw[t+0], eb[(size_t)(t+0)*E_], a0);
        a1 = fmaf(sw[t+1], eb[(size_t)(t+1)*E_], a1);
        a2 = fmaf(sw[t+2], eb[(size_t)(t+2)*E_], a2);
        a3 = fmaf(sw[t+3], eb[(size_t)(t+3)*E_], a3);
    }
    out[OUT_CTX + b*E_ + ec] = (a0+a1)+(a2+a3);
}

// ---------------------------------------------------------------------------
extern "C" void kernel_launch(void* const* d_in, const int* in_sizes, int n_in,
                              void* d_out, int out_size)
{
    const float* enc      = (const float*)d_in[0];
    const int*   len      = (const int*)  d_in[1];
    const float* dec_z    = (const float*)d_in[2];
    const float* att_prev = (const float*)d_in[3];
    const float* att_h    = (const float*)d_in[4];
    const float* att_c    = (const float*)d_in[5];
    const float* W_enc    = (const float*)d_in[6];
    const float* b_enc    = (const float*)d_in[7];
    const float* W_dec    = (const float*)d_in[8];
    const float* conv_w   = (const float*)d_in[9];
    const float* W_ih     = (const float*)d_in[10];
    const float* W_hh     = (const float*)d_in[11];
    const float* W_g      = (const float*)d_in[12];
    const float* b_g      = (const float*)d_in[13];
    float* out = (float*)d_out;

    transpose_kernel<<<dim3(E_/32, A_/32), dim3(32,8)>>>(W_enc);
    conv_kernel<<<dim3(B_, C_), 256>>>(att_prev, conv_w);
    lstm_kernel<<<B_, 512>>>(dec_z, att_h, att_c, b_enc, W_dec, W_ih, W_hh, out);
    score_kernel<<<dim3(T_/32, B_), 256>>>(enc, W_g, b_g);
    softmax_kernel<<<B_, 256>>>(len, out);
    ctx_kernel<<<dim3(B_, E_/256), 256>>>(enc, out);
}

// round 3
// speedup vs baseline: 1.8329x; 1.8329x over previous
#include <cuda_runtime.h>
#include <cuda_bf16.h>
#include <cstdint>
#include <math.h>

#define B_   32
#define T_   1600
#define E_   1024
#define D_   1024
#define A_   512
#define C_   10
#define KW   201
#define FILTR 100

// output layout: ctx (B,E), w (B,T), h_new (B,A), c_new (B,A)
#define OUT_CTX 0
#define OUT_W   (B_*E_)
#define OUT_H   (OUT_W + B_*T_)
#define OUT_CN  (OUT_H + B_*A_)

// GEMM tiling
#define MT   128                  // t-rows per CTA
#define NT   128                  // a-cols per CTA
#define KC   64                   // k elems per chunk (128B bf16 row)
#define NKT  (E_/KC)              // 16 chunks
#define MTILES ((T_ + MT - 1)/MT) // 13
#define NSTAGE 3

// stage layout: Ah, Al, Bh, Bl tiles of 128 rows x 128B
#define TILE_BYTES (128*128)
#define OFF_AH 0
#define OFF_AL (1*TILE_BYTES)
#define OFF_BH (2*TILE_BYTES)
#define OFF_BL (3*TILE_BYTES)
#define STAGE_BYTES (4*TILE_BYTES)          // 64KB
#define SMEM_DYN (NSTAGE*STAGE_BYTES)       // 192KB

// -------- scratch (__device__ globals, zero-initialized) --------
__device__ __nv_bfloat16 g_eh[(size_t)(B_*T_ + MT) * E_];  // enc hi (pad rows 0)
__device__ __nv_bfloat16 g_el[(size_t)(B_*T_ + MT) * E_];  // enc lo
__device__ __nv_bfloat16 g_wh[(size_t)A_ * E_];            // W_enc hi ([A,E] k-major)
__device__ __nv_bfloat16 g_wl[(size_t)A_ * E_];            // W_enc lo
__device__ float g_feat[B_*C_];
__device__ float g_sv[B_*A_];       // h_new + dec_proj + b_enc
__device__ float g_e[B_*T_];        // scores (atomic-accumulated)

static __device__ __forceinline__ float sigmf(float x){ return 1.0f/(1.0f+expf(-x)); }

static __device__ __forceinline__ unsigned smem_u32(const void* p){
    return (unsigned)__cvta_generic_to_shared(p);
}
static __device__ __forceinline__ void cp16(unsigned d, const void* s){
    asm volatile("cp.async.cg.shared.global [%0], [%1], 16;" :: "r"(d), "l"(s));
}
static __device__ __forceinline__ void ldsm4(uint32_t r[4], uint32_t addr){
    asm volatile("ldmatrix.sync.aligned.m8n8.x4.shared.b16 {%0,%1,%2,%3}, [%4];"
                 : "=r"(r[0]), "=r"(r[1]), "=r"(r[2]), "=r"(r[3]) : "r"(addr));
}
static __device__ __forceinline__ void mma16816(float c[4], const uint32_t a[4],
                                                uint32_t b0, uint32_t b1){
    asm volatile("mma.sync.aligned.m16n8k16.row.col.f32.bf16.bf16.f32 "
                 "{%0,%1,%2,%3}, {%4,%5,%6,%7}, {%8,%9}, {%0,%1,%2,%3};"
                 : "+f"(c[0]), "+f"(c[1]), "+f"(c[2]), "+f"(c[3])
                 : "r"(a[0]), "r"(a[1]), "r"(a[2]), "r"(a[3]), "r"(b0), "r"(b1));
}

// ---------------------------------------------------------------------------
// bf16 hi/lo split kernels
// ---------------------------------------------------------------------------
__global__ void split_w_kernel(const float* __restrict__ W){
    int i = blockIdx.x*blockDim.x + threadIdx.x;   // float4 index, exact grid
    float4 v = ((const float4*)W)[i];
    __nv_bfloat162 h0 = __floats2bfloat162_rn(v.x, v.y);
    __nv_bfloat162 h1 = __floats2bfloat162_rn(v.z, v.w);
    float4 r;
    r.x = v.x - __bfloat162float(h0.x);
    r.y = v.y - __bfloat162float(h0.y);
    r.z = v.z - __bfloat162float(h1.x);
    r.w = v.w - __bfloat162float(h1.y);
    __nv_bfloat162 l0 = __floats2bfloat162_rn(r.x, r.y);
    __nv_bfloat162 l1 = __floats2bfloat162_rn(r.z, r.w);
    ((__nv_bfloat162*)g_wh)[2*i]   = h0;
    ((__nv_bfloat162*)g_wh)[2*i+1] = h1;
    ((__nv_bfloat162*)g_wl)[2*i]   = l0;
    ((__nv_bfloat162*)g_wl)[2*i+1] = l1;
}

__global__ void split_enc_kernel(const float* __restrict__ enc){
    const int n4 = B_*T_*E_/4;
    int stride = gridDim.x*blockDim.x;
    for (int i = blockIdx.x*blockDim.x + threadIdx.x; i < n4; i += stride){
        float4 v = ((const float4*)enc)[i];
        __nv_bfloat162 h0 = __floats2bfloat162_rn(v.x, v.y);
        __nv_bfloat162 h1 = __floats2bfloat162_rn(v.z, v.w);
        float4 r;
        r.x = v.x - __bfloat162float(h0.x);
        r.y = v.y - __bfloat162float(h0.y);
        r.z = v.z - __bfloat162float(h1.x);
        r.w = v.w - __bfloat162float(h1.y);
        __nv_bfloat162 l0 = __floats2bfloat162_rn(r.x, r.y);
        __nv_bfloat162 l1 = __floats2bfloat162_rn(r.z, r.w);
        ((__nv_bfloat162*)g_eh)[2*i]   = h0;
        ((__nv_bfloat162*)g_eh)[2*i+1] = h1;
        ((__nv_bfloat162*)g_el)[2*i]   = l0;
        ((__nv_bfloat162*)g_el)[2*i+1] = l1;
    }
}

__global__ void zero_e_kernel(){
    int i = blockIdx.x*blockDim.x + threadIdx.x;
    if (i < B_*T_) g_e[i] = 0.f;
}

// ---------------------------------------------------------------------------
// conv + relu + global max-pool -> g_feat
// ---------------------------------------------------------------------------
__global__ void conv_kernel(const float* __restrict__ ap, const float* __restrict__ cw){
    __shared__ float xp[T_ + 2*FILTR];
    __shared__ float wk[KW];
    __shared__ float red[256];
    int b = blockIdx.x, c = blockIdx.y, tid = threadIdx.x;
    for (int i=tid;i<T_+2*FILTR;i+=256){
        int t = i - FILTR;
        xp[i] = (t>=0 && t<T_) ? ap[b*T_+t] : 0.f;
    }
    for (int i=tid;i<KW;i+=256) wk[i] = cw[c*KW + i];
    __syncthreads();
    float m = 0.f;
    for (int t=tid;t<T_;t+=256){
        float acc = 0.f;
        #pragma unroll 4
        for (int k=0;k<KW;k++) acc = fmaf(xp[t+k], wk[k], acc);
        m = fmaxf(m, acc);
    }
    red[tid]=m; __syncthreads();
    for (int s=128;s>0;s>>=1){ if (tid<s) red[tid]=fmaxf(red[tid],red[tid+s]); __syncthreads(); }
    if (tid==0) g_feat[b*C_+c] = red[0];
}

// ---------------------------------------------------------------------------
// LSTM cell + dec_proj + sv
// ---------------------------------------------------------------------------
__global__ __launch_bounds__(512) void lstm_kernel(
    const float* __restrict__ dec_z, const float* __restrict__ att_h,
    const float* __restrict__ att_c, const float* __restrict__ b_enc,
    const float* __restrict__ W_dec, const float* __restrict__ W_ih,
    const float* __restrict__ W_hh, float* __restrict__ out)
{
    __shared__ float s_feat[16];
    __shared__ float s_h[A_];
    __shared__ float s_z[D_];
    __shared__ float s_g[4*A_];
    __shared__ float s_hn[A_];
    int b = blockIdx.x, tid = threadIdx.x;
    int lane = tid & 31, wp = tid >> 5;
    if (tid < C_) s_feat[tid] = g_feat[b*C_+tid];
    s_h[tid] = att_h[b*A_+tid];
    s_z[tid] = dec_z[b*D_+tid];
    s_z[tid+512] = dec_z[b*D_+tid+512];
    __syncthreads();
    for (int r = wp; r < 4*A_; r += 16){
        float acc = 0.f;
        const float* wr = &W_hh[(size_t)r*A_];
        for (int a=lane;a<A_;a+=32) acc = fmaf(s_h[a], wr[a], acc);
        if (lane < C_) acc = fmaf(s_feat[lane], W_ih[r*C_+lane], acc);
        #pragma unroll
        for (int o=16;o>0;o>>=1) acc += __shfl_xor_sync(0xffffffffu, acc, o);
        if (lane==0) s_g[r] = acc;
    }
    __syncthreads();
    {
        int a = tid;
        float ig=s_g[a], fg=s_g[A_+a], gg=s_g[2*A_+a], og=s_g[3*A_+a];
        float cn = sigmf(fg)*att_c[b*A_+a] + sigmf(ig)*tanhf(gg);
        float hn = sigmf(og)*tanhf(cn);
        out[OUT_H  + b*A_ + a] = hn;
        out[OUT_CN + b*A_ + a] = cn;
        s_hn[a] = hn;
    }
    __syncthreads();
    for (int r = wp; r < A_; r += 16){
        float acc = 0.f;
        const float* wr = &W_dec[(size_t)r*D_];
        for (int d=lane;d<D_;d+=32) acc = fmaf(s_z[d], wr[d], acc);
        #pragma unroll
        for (int o=16;o>0;o>>=1) acc += __shfl_xor_sync(0xffffffffu, acc, o);
        if (lane==0) g_sv[b*A_+r] = acc + s_hn[r] + b_enc[r];
    }
}

// ---------------------------------------------------------------------------
// HMMA score kernel: one 128(t) x 128(a) tile of
//   D = Ah*Bh + Ah*Bl + Al*Bh  (fp32 accum), then
//   e_part[t] = sum_a Wg[a]*tanh(D[t,a]+sv[a]); atomicAdd into g_e.
// 256 threads = 8 warps (4m x 2n), warp tile 32x64.
// 3-stage cp.async pipeline, SW128-swizzled tiles.
// ---------------------------------------------------------------------------
__global__ __launch_bounds__(256) void score_kernel(const float* __restrict__ Wg)
{
    extern __shared__ char smem[];
    __shared__ float s_sv[NT];
    __shared__ float s_wg[NT];
    const uint32_t sb0 = smem_u32(smem);
    const int tid = threadIdx.x;
    const int lane = tid & 31, wid = tid >> 5;
    const int warp_m = wid >> 1, warp_n = wid & 1;
    const int b  = blockIdx.z;
    const int t0 = blockIdx.x * MT;
    const int a0 = blockIdx.y * NT;

    if (tid < NT){ s_sv[tid] = g_sv[b*A_ + a0 + tid]; s_wg[tid] = Wg[a0 + tid]; }

    const __nv_bfloat16* pAh = g_eh + (size_t)(b*T_ + t0)*E_;
    const __nv_bfloat16* pAl = g_el + (size_t)(b*T_ + t0)*E_;
    const __nv_bfloat16* pBh = g_wh + (size_t)a0*E_;
    const __nv_bfloat16* pBl = g_wl + (size_t)a0*E_;

    // cp.async per-thread pattern: 4 chunks per tile
    const int crow = tid >> 3;            // 0..31 (row within 32-row group)
    const int cch  = tid & 7;             // 16B chunk 0..7

    auto load_stage = [&](int st, int kt){
        const uint32_t sb = sb0 + st*STAGE_BYTES;
        const int kof = kt*KC;
        #pragma unroll
        for (int j=0;j<4;j++){
            int row = j*32 + crow;
            uint32_t off = (uint32_t)row*128 + (uint32_t)((cch ^ (row & 7)) << 4);
            size_t so = (size_t)row*E_ + kof + cch*8;
            cp16(sb + OFF_AH + off, pAh + so);
            cp16(sb + OFF_AL + off, pAl + so);
            cp16(sb + OFF_BH + off, pBh + so);
            cp16(sb + OFF_BL + off, pBl + so);
        }
        asm volatile("cp.async.commit_group;" ::: "memory");
    };

    // ldmatrix per-lane row offsets (row fixed per lane; chunk varies by k16)
    const int lrow = lane & 15, lsel = lane >> 4;   // lsel: k16 halves
    const int arow0 = warp_m*32 + lrow;             // m-frag 0
    const int arow1 = arow0 + 16;                   // m-frag 1
    const int brow0 = warp_n*64 + lrow;             // n-groups 0..3 add g*16
    const uint32_t aoffr0 = (uint32_t)arow0*128, asx0 = arow0 & 7;
    const uint32_t aoffr1 = (uint32_t)arow1*128, asx1 = arow1 & 7;
    uint32_t boffr[4], bsx[4];
    #pragma unroll
    for (int g=0; g<4; g++){
        int r = brow0 + g*16;
        boffr[g] = (uint32_t)r*128; bsx[g] = r & 7;
    }

    float acc[2][8][4];
    #pragma unroll
    for (int i=0;i<2;i++)
        #pragma unroll
        for (int j=0;j<8;j++)
            #pragma unroll
            for (int k=0;k<4;k++) acc[i][j][k] = 0.f;

    load_stage(0, 0);
    load_stage(1, 1);

    #pragma unroll 1
    for (int kt = 0; kt < NKT; kt++){
        asm volatile("cp.async.wait_group 1;" ::: "memory");
        __syncthreads();
        if (kt + 2 < NKT) load_stage((kt+2)%NSTAGE, kt+2);

        const uint32_t sb = sb0 + (kt%NSTAGE)*STAGE_BYTES;
        #pragma unroll
        for (int k16=0; k16<4; k16++){
            const int ch = k16*2 + lsel;
            uint32_t Ah0[4], Ah1[4], Al0[4], Al1[4];
            uint32_t ao0 = aoffr0 + ((uint32_t)(ch ^ asx0) << 4);
            uint32_t ao1 = aoffr1 + ((uint32_t)(ch ^ asx1) << 4);
            ldsm4(Ah0, sb + OFF_AH + ao0);
            ldsm4(Ah1, sb + OFF_AH + ao1);
            ldsm4(Al0, sb + OFF_AL + ao0);
            ldsm4(Al1, sb + OFF_AL + ao1);
            #pragma unroll
            for (int g=0; g<4; g++){
                uint32_t bo = boffr[g] + ((uint32_t)(ch ^ bsx[g]) << 4);
                uint32_t Bh[4], Bl[4];
                ldsm4(Bh, sb + OFF_BH + bo);
                ldsm4(Bl, sb + OFF_BL + bo);
                // n-frag 2g  uses regs {0,2}; n-frag 2g+1 uses {1,3}
                mma16816(acc[0][2*g],   Ah0, Bh[0], Bh[2]);
                mma16816(acc[0][2*g+1], Ah0, Bh[1], Bh[3]);
                mma16816(acc[1][2*g],   Ah1, Bh[0], Bh[2]);
                mma16816(acc[1][2*g+1], Ah1, Bh[1], Bh[3]);
                mma16816(acc[0][2*g],   Ah0, Bl[0], Bl[2]);
                mma16816(acc[0][2*g+1], Ah0, Bl[1], Bl[3]);
                mma16816(acc[1][2*g],   Ah1, Bl[0], Bl[2]);
                mma16816(acc[1][2*g+1], Ah1, Bl[1], Bl[3]);
                mma16816(acc[0][2*g],   Al0, Bh[0], Bh[2]);
                mma16816(acc[0][2*g+1], Al0, Bh[1], Bh[3]);
                mma16816(acc[1][2*g],   Al1, Bh[0], Bh[2]);
                mma16816(acc[1][2*g+1], Al1, Bh[1], Bh[3]);
            }
        }
        __syncthreads();
    }

    // epilogue
    const int qh = lane >> 2, qr = lane & 3;
    #pragma unroll
    for (int mi=0; mi<2; mi++){
        float p0 = 0.f, p1 = 0.f;
        #pragma unroll
        for (int nf=0; nf<8; nf++){
            int a = warp_n*64 + nf*8 + 2*qr;
            const float* c = acc[mi][nf];
            p0 = fmaf(s_wg[a],   tanhf(c[0] + s_sv[a]),   p0);
            p0 = fmaf(s_wg[a+1], tanhf(c[1] + s_sv[a+1]), p0);
            p1 = fmaf(s_wg[a],   tanhf(c[2] + s_sv[a]),   p1);
            p1 = fmaf(s_wg[a+1], tanhf(c[3] + s_sv[a+1]), p1);
        }
        p0 += __shfl_xor_sync(0xffffffffu, p0, 1);
        p0 += __shfl_xor_sync(0xffffffffu, p0, 2);
        p1 += __shfl_xor_sync(0xffffffffu, p1, 1);
        p1 += __shfl_xor_sync(0xffffffffu, p1, 2);
        if (qr == 0){
            int t = t0 + warp_m*32 + mi*16 + qh;
            if (t < T_)     atomicAdd(&g_e[b*T_ + t],     p0);
            if (t+8 < T_)   atomicAdd(&g_e[b*T_ + t + 8], p1);
        }
    }
}

// ---------------------------------------------------------------------------
// masked scaled softmax (b_g cancels in softmax -> dropped)
// ---------------------------------------------------------------------------
__global__ void softmax_kernel(const int* __restrict__ len, float* __restrict__ out){
    __shared__ float se[T_];
    __shared__ float red[256];
    int b = blockIdx.x, tid = threadIdx.x;
    int L = len[b];
    for (int t=tid;t<T_;t+=256) se[t] = g_e[b*T_+t];
    __syncthreads();
    float m = -3.4e38f;
    for (int t=tid;t<L;t+=256) m = fmaxf(m, se[t]);
    red[tid]=m; __syncthreads();
    for (int s=128;s>0;s>>=1){ if (tid<s) red[tid]=fmaxf(red[tid],red[tid+s]); __syncthreads(); }
    m = red[0];
    __syncthreads();
    float sum = 0.f;
    for (int t=tid;t<T_;t+=256){
        float v = (t<L) ? expf(2.0f*(se[t]-m)) : 0.f;
        se[t] = v;
        sum += v;
    }
    red[tid]=sum; __syncthreads();
    for (int s=128;s>0;s>>=1){ if (tid<s) red[tid]+=red[tid+s]; __syncthreads(); }
    float inv = 1.0f/red[0];
    for (int t=tid;t<T_;t+=256) out[OUT_W + b*T_ + t] = se[t]*inv;
}

// ---------------------------------------------------------------------------
// ctx = w @ enc
// ---------------------------------------------------------------------------
__global__ void ctx_kernel(const float* __restrict__ enc, float* __restrict__ out){
    __shared__ float sw[T_];
    int b = blockIdx.x;
    int ec = blockIdx.y*256 + threadIdx.x;
    for (int t=threadIdx.x;t<T_;t+=256) sw[t] = out[OUT_W + b*T_ + t];
    __syncthreads();
    const float* eb = enc + (size_t)b*T_*E_ + ec;
    float a0=0.f,a1=0.f,a2=0.f,a3=0.f,a4=0.f,a5=0.f,a6=0.f,a7=0.f;
    #pragma unroll 1
    for (int t=0;t<T_;t+=8){
        a0 = fmaf(sw[t+0], eb[(size_t)(t+0)*E_], a0);
        a1 = fmaf(sw[t+1], eb[(size_t)(t+1)*E_], a1);
        a2 = fmaf(sw[t+2], eb[(size_t)(t+2)*E_], a2);
        a3 = fmaf(sw[t+3], eb[(size_t)(t+3)*E_], a3);
        a4 = fmaf(sw[t+4], eb[(size_t)(t+4)*E_], a4);
        a5 = fmaf(sw[t+5], eb[(size_t)(t+5)*E_], a5);
        a6 = fmaf(sw[t+6], eb[(size_t)(t+6)*E_], a6);
        a7 = fmaf(sw[t+7], eb[(size_t)(t+7)*E_], a7);
    }
    out[OUT_CTX + b*E_ + ec] = ((a0+a1)+(a2+a3)) + ((a4+a5)+(a6+a7));
}

// ---------------------------------------------------------------------------
extern "C" void kernel_launch(void* const* d_in, const int* in_sizes, int n_in,
                              void* d_out, int out_size)
{
    const float* enc      = (const float*)d_in[0];
    const int*   len      = (const int*)  d_in[1];
    const float* dec_z    = (const float*)d_in[2];
    const float* att_prev = (const float*)d_in[3];
    const float* att_h    = (const float*)d_in[4];
    const float* att_c    = (const float*)d_in[5];
    const float* W_enc    = (const float*)d_in[6];
    const float* b_enc    = (const float*)d_in[7];
    const float* W_dec    = (const float*)d_in[8];
    const float* conv_w   = (const float*)d_in[9];
    const float* W_ih     = (const float*)d_in[10];
    const float* W_hh     = (const float*)d_in[11];
    const float* W_g      = (const float*)d_in[12];
    float* out = (float*)d_out;

    cudaFuncSetAttribute(score_kernel,
                         cudaFuncAttributeMaxDynamicSharedMemorySize, SMEM_DYN);

    split_w_kernel<<<A_*E_/4/256, 256>>>(W_enc);
    split_enc_kernel<<<4096, 256>>>(enc);
    zero_e_kernel<<<(B_*T_+1023)/1024, 1024>>>();
    conv_kernel<<<dim3(B_, C_), 256>>>(att_prev, conv_w);
    lstm_kernel<<<B_, 512>>>(dec_z, att_h, att_c, b_enc, W_dec, W_ih, W_hh, out);
    score_kernel<<<dim3(MTILES, A_/NT, B_), 256, SMEM_DYN>>>(W_g);
    softmax_kernel<<<B_, 256>>>(len, out);
    ctx_kernel<<<dim3(B_, E_/256), 256>>>(enc, out);
}

// round 4
// speedup vs baseline: 1.9920x; 1.0868x over previous
#include <cuda_runtime.h>
#include <cuda_bf16.h>
#include <cstdint>
#include <math.h>

#define B_   32
#define T_   1600
#define E_   1024
#define D_   1024
#define A_   512
#define C_   10
#define KW   201
#define FILTR 100

// output layout: ctx (B,E), w (B,T), h_new (B,A), c_new (B,A)
#define OUT_CTX 0
#define OUT_W   (B_*E_)
#define OUT_H   (OUT_W + B_*T_)
#define OUT_CN  (OUT_H + B_*A_)

// GEMM tiling
#define MT   128
#define NT   128
#define KC   64                   // k elems per chunk
#define NKT  (E_/KC)              // 16
#define MTILES ((T_ + MT - 1)/MT) // 13

// dynamic smem layout (bytes):
//  f32 A staging: 2 stages x 32KB   @ 0
//  Ah/Al bf16:    2 stages x 32KB   @ 64KB   (Ah +0, Al +16KB)
//  Bh/Bl bf16:    3 stages x 32KB   @ 128KB  (Bh +0, Bl +16KB)
#define OFF_A32(st) ((st)*32768)
#define OFF_AH(st)  (65536 + (st)*32768)
#define OFF_AL(st)  (65536 + (st)*32768 + 16384)
#define OFF_B(st)   (131072 + (st)*32768)
#define SMEM_DYN    229376

// -------- scratch --------
__device__ __nv_bfloat16 g_wh[(size_t)A_ * E_];
__device__ __nv_bfloat16 g_wl[(size_t)A_ * E_];
__device__ float g_feat[B_*C_];
__device__ float g_sv[B_*A_];
__device__ float g_e[B_*T_];

static __device__ __forceinline__ float sigmf(float x){ return 1.0f/(1.0f+expf(-x)); }
static __device__ __forceinline__ unsigned smem_u32(const void* p){
    return (unsigned)__cvta_generic_to_shared(p);
}
static __device__ __forceinline__ void cp16(unsigned d, const void* s){
    asm volatile("cp.async.cg.shared.global [%0], [%1], 16;" :: "r"(d), "l"(s));
}
static __device__ __forceinline__ void ldsm4(uint32_t r[4], uint32_t addr){
    asm volatile("ldmatrix.sync.aligned.m8n8.x4.shared.b16 {%0,%1,%2,%3}, [%4];"
                 : "=r"(r[0]), "=r"(r[1]), "=r"(r[2]), "=r"(r[3]) : "r"(addr));
}
static __device__ __forceinline__ void mma16816(float c[4], const uint32_t a[4],
                                                uint32_t b0, uint32_t b1){
    asm volatile("mma.sync.aligned.m16n8k16.row.col.f32.bf16.bf16.f32 "
                 "{%0,%1,%2,%3}, {%4,%5,%6,%7}, {%8,%9}, {%0,%1,%2,%3};"
                 : "+f"(c[0]), "+f"(c[1]), "+f"(c[2]), "+f"(c[3])
                 : "r"(a[0]), "r"(a[1]), "r"(a[2]), "r"(a[3]), "r"(b0), "r"(b1));
}

// ---------------------------------------------------------------------------
// split W_enc into bf16 hi/lo (tiny: 2MB)
// ---------------------------------------------------------------------------
__global__ void split_w_kernel(const float* __restrict__ W){
    int i = blockIdx.x*blockDim.x + threadIdx.x;   // float4 index, exact grid
    float4 v = ((const float4*)W)[i];
    __nv_bfloat162 h0 = __floats2bfloat162_rn(v.x, v.y);
    __nv_bfloat162 h1 = __floats2bfloat162_rn(v.z, v.w);
    float r0 = v.x - __bfloat162float(h0.x);
    float r1 = v.y - __bfloat162float(h0.y);
    float r2 = v.z - __bfloat162float(h1.x);
    float r3 = v.w - __bfloat162float(h1.y);
    __nv_bfloat162 l0 = __floats2bfloat162_rn(r0, r1);
    __nv_bfloat162 l1 = __floats2bfloat162_rn(r2, r3);
    ((__nv_bfloat162*)g_wh)[2*i]   = h0;
    ((__nv_bfloat162*)g_wh)[2*i+1] = h1;
    ((__nv_bfloat162*)g_wl)[2*i]   = l0;
    ((__nv_bfloat162*)g_wl)[2*i+1] = l1;
}

// zero g_e and the ctx region of out (both atomic-accumulated)
__global__ void zero_kernel(float* __restrict__ out){
    int i = blockIdx.x*blockDim.x + threadIdx.x;
    if (i < B_*T_) g_e[i] = 0.f;
    if (i < B_*E_) out[OUT_CTX + i] = 0.f;
}

// ---------------------------------------------------------------------------
// conv + relu + global max-pool, register sliding window (4 t / thread)
// ---------------------------------------------------------------------------
__global__ void conv_kernel(const float* __restrict__ ap, const float* __restrict__ cw){
    __shared__ float xp[1808];
    __shared__ float wk[KW+3];
    __shared__ float red[256];
    int b = blockIdx.x, c = blockIdx.y, tid = threadIdx.x;
    for (int i=tid;i<1808;i+=256){
        int t = i - FILTR;
        xp[i] = (t>=0 && t<T_) ? ap[b*T_+t] : 0.f;
    }
    for (int i=tid;i<KW+3;i+=256) wk[i] = (i<KW) ? cw[c*KW + i] : 0.f;
    __syncthreads();
    float m = 0.f;
    #pragma unroll
    for (int p=0;p<2;p++){
        int grp = p*256 + tid;
        if (grp < 400){
            int t0 = grp*4;
            float x0=xp[t0], x1=xp[t0+1], x2=xp[t0+2], x3=xp[t0+3];
            float a0=0.f,a1=0.f,a2=0.f,a3=0.f;
            #pragma unroll 4
            for (int k=0;k<KW;k++){
                float w = wk[k];
                a0 = fmaf(x0, w, a0);
                a1 = fmaf(x1, w, a1);
                a2 = fmaf(x2, w, a2);
                a3 = fmaf(x3, w, a3);
                x0=x1; x1=x2; x2=x3; x3=xp[t0+k+4];
            }
            m = fmaxf(m, fmaxf(fmaxf(a0,a1), fmaxf(a2,a3)));
        }
    }
    red[tid]=m; __syncthreads();
    for (int s=128;s>0;s>>=1){ if (tid<s) red[tid]=fmaxf(red[tid],red[tid+s]); __syncthreads(); }
    if (tid==0) g_feat[b*C_+c] = red[0];
}

// ---------------------------------------------------------------------------
// LSTM cell + dec_proj + sv
// ---------------------------------------------------------------------------
__global__ __launch_bounds__(512) void lstm_kernel(
    const float* __restrict__ dec_z, const float* __restrict__ att_h,
    const float* __restrict__ att_c, const float* __restrict__ b_enc,
    const float* __restrict__ W_dec, const float* __restrict__ W_ih,
    const float* __restrict__ W_hh, float* __restrict__ out)
{
    __shared__ float s_feat[16];
    __shared__ float s_h[A_];
    __shared__ float s_z[D_];
    __shared__ float s_g[4*A_];
    __shared__ float s_hn[A_];
    int b = blockIdx.x, tid = threadIdx.x;
    int lane = tid & 31, wp = tid >> 5;
    if (tid < C_) s_feat[tid] = g_feat[b*C_+tid];
    s_h[tid] = att_h[b*A_+tid];
    s_z[tid] = dec_z[b*D_+tid];
    s_z[tid+512] = dec_z[b*D_+tid+512];
    __syncthreads();
    for (int r = wp; r < 4*A_; r += 16){
        float acc = 0.f;
        const float* wr = &W_hh[(size_t)r*A_];
        for (int a=lane;a<A_;a+=32) acc = fmaf(s_h[a], wr[a], acc);
        if (lane < C_) acc = fmaf(s_feat[lane], W_ih[r*C_+lane], acc);
        #pragma unroll
        for (int o=16;o>0;o>>=1) acc += __shfl_xor_sync(0xffffffffu, acc, o);
        if (lane==0) s_g[r] = acc;
    }
    __syncthreads();
    {
        int a = tid;
        float ig=s_g[a], fg=s_g[A_+a], gg=s_g[2*A_+a], og=s_g[3*A_+a];
        float cn = sigmf(fg)*att_c[b*A_+a] + sigmf(ig)*tanhf(gg);
        float hn = sigmf(og)*tanhf(cn);
        out[OUT_H  + b*A_ + a] = hn;
        out[OUT_CN + b*A_ + a] = cn;
        s_hn[a] = hn;
    }
    __syncthreads();
    for (int r = wp; r < A_; r += 16){
        float acc = 0.f;
        const float* wr = &W_dec[(size_t)r*D_];
        for (int d=lane;d<D_;d+=32) acc = fmaf(s_z[d], wr[d], acc);
        #pragma unroll
        for (int o=16;o>0;o>>=1) acc += __shfl_xor_sync(0xffffffffu, acc, o);
        if (lane==0) g_sv[b*A_+r] = acc + s_hn[r] + b_enc[r];
    }
}

// ---------------------------------------------------------------------------
// HMMA score kernel with in-kernel enc hi/lo split.
//   D = Ah*Bh + Ah*Bl + Al*Bh; e_part[t] = sum_a Wg[a]*tanh(D+sv); atomicAdd.
// 256 threads = 8 warps (4m x 2n), warp tile 32x64.
// ---------------------------------------------------------------------------
__global__ __launch_bounds__(256) void score_kernel(const float* __restrict__ enc,
                                                    const float* __restrict__ Wg)
{
    extern __shared__ char smemc[];
    __shared__ float s_sv[NT];
    __shared__ float s_wg[NT];
    const uint32_t sb0 = smem_u32(smemc);
    const int tid = threadIdx.x;
    const int lane = tid & 31, wid = tid >> 5;
    const int warp_m = wid >> 1, warp_n = wid & 1;
    const int b  = blockIdx.z;
    const int t0 = blockIdx.x * MT;
    const int a0 = blockIdx.y * NT;

    if (tid < NT){ s_sv[tid] = g_sv[b*A_ + a0 + tid]; s_wg[tid] = Wg[a0 + tid]; }

    const float* encb = enc + (size_t)b*T_*E_;
    const __nv_bfloat16* pBh = g_wh + (size_t)a0*E_;
    const __nv_bfloat16* pBl = g_wl + (size_t)a0*E_;

    auto load_stage = [&](int kt){
        const int stA = kt & 1, stB = kt % 3;
        const int kof = kt*KC;
        // f32 A tile: 128 rows x 256B
        #pragma unroll
        for (int j=0;j<8;j++){
            int idx = j*256 + tid;
            int row = idx >> 4, ch = idx & 15;
            int trow = t0 + row; if (trow >= T_) trow = T_-1;   // clamp (discarded rows)
            cp16(sb0 + OFF_A32(stA) + row*256 + ch*16,
                 encb + (size_t)trow*E_ + kof + ch*4);
        }
        // B bf16 tiles: 128 rows x 128B, SW128
        #pragma unroll
        for (int j=0;j<4;j++){
            int idx = j*256 + tid;
            int row = idx >> 3, ch = idx & 7;
            uint32_t off = (uint32_t)row*128 + (uint32_t)((ch ^ (row & 7)) << 4);
            size_t so = (size_t)row*E_ + kof + ch*8;
            cp16(sb0 + OFF_B(stB) + off,         pBh + so);
            cp16(sb0 + OFF_B(stB) + 16384 + off, pBl + so);
        }
        asm volatile("cp.async.commit_group;" ::: "memory");
    };

    // ldmatrix per-lane addressing
    const int lrow = lane & 15, lsel = lane >> 4;
    const int arow0 = warp_m*32 + lrow, arow1 = arow0 + 16;
    const uint32_t aoffr0 = (uint32_t)arow0*128, asx0 = arow0 & 7;
    const uint32_t aoffr1 = (uint32_t)arow1*128, asx1 = arow1 & 7;
    uint32_t boffr[4], bsx[4];
    #pragma unroll
    for (int g=0; g<4; g++){
        int r = warp_n*64 + lrow + g*16;
        boffr[g] = (uint32_t)r*128; bsx[g] = r & 7;
    }

    float acc[2][8][4];
    #pragma unroll
    for (int i=0;i<2;i++)
        #pragma unroll
        for (int j=0;j<8;j++)
            #pragma unroll
            for (int k=0;k<4;k++) acc[i][j][k] = 0.f;

    load_stage(0);
    load_stage(1);

    #pragma unroll 1
    for (int kt = 0; kt < NKT; kt++){
        if (kt == NKT-1) asm volatile("cp.async.wait_group 0;" ::: "memory");
        else             asm volatile("cp.async.wait_group 1;" ::: "memory");
        __syncthreads();

        const int stA = kt & 1, stB = kt % 3;
        // convert f32 A tile -> swizzled bf16 hi/lo tiles
        {
            const char* a32 = smemc + OFF_A32(stA);
            char* ah = smemc + OFF_AH(stA);
            char* al = smemc + OFF_AL(stA);
            #pragma unroll
            for (int p=0;p<8;p++){
                int f4i = p*256 + tid;          // 0..2047
                int row = f4i >> 4, c4 = f4i & 15;
                float4 v = *(const float4*)(a32 + row*256 + c4*16);
                __nv_bfloat162 h0 = __floats2bfloat162_rn(v.x, v.y);
                __nv_bfloat162 h1 = __floats2bfloat162_rn(v.z, v.w);
                float r0 = v.x - __bfloat162float(h0.x);
                float r1 = v.y - __bfloat162float(h0.y);
                float r2 = v.z - __bfloat162float(h1.x);
                float r3 = v.w - __bfloat162float(h1.y);
                __nv_bfloat162 l0 = __floats2bfloat162_rn(r0, r1);
                __nv_bfloat162 l1 = __floats2bfloat162_rn(r2, r3);
                uint32_t boff = (uint32_t)row*128
                              + (uint32_t)(((c4>>1) ^ (row & 7)) << 4)
                              + (uint32_t)((c4 & 1) * 8);
                uint2 hh, ll;
                hh.x = *reinterpret_cast<uint32_t*>(&h0);
                hh.y = *reinterpret_cast<uint32_t*>(&h1);
                ll.x = *reinterpret_cast<uint32_t*>(&l0);
                ll.y = *reinterpret_cast<uint32_t*>(&l1);
                *(uint2*)(ah + boff) = hh;
                *(uint2*)(al + boff) = ll;
            }
        }
        __syncthreads();

        if (kt + 2 < NKT) load_stage(kt+2);

        const uint32_t sAh = sb0 + OFF_AH(stA);
        const uint32_t sAl = sb0 + OFF_AL(stA);
        const uint32_t sBh = sb0 + OFF_B(stB);
        const uint32_t sBl = sBh + 16384;
        #pragma unroll
        for (int k16=0; k16<4; k16++){
            const int ch = k16*2 + lsel;
            uint32_t Ah0[4], Ah1[4], Al0[4], Al1[4];
            uint32_t ao0 = aoffr0 + ((uint32_t)(ch ^ asx0) << 4);
            uint32_t ao1 = aoffr1 + ((uint32_t)(ch ^ asx1) << 4);
            ldsm4(Ah0, sAh + ao0);
            ldsm4(Ah1, sAh + ao1);
            ldsm4(Al0, sAl + ao0);
            ldsm4(Al1, sAl + ao1);
            #pragma unroll
            for (int g=0; g<4; g++){
                uint32_t bo = boffr[g] + ((uint32_t)(ch ^ bsx[g]) << 4);
                uint32_t Bh[4], Bl[4];
                ldsm4(Bh, sBh + bo);
                ldsm4(Bl, sBl + bo);
                mma16816(acc[0][2*g],   Ah0, Bh[0], Bh[2]);
                mma16816(acc[0][2*g+1], Ah0, Bh[1], Bh[3]);
                mma16816(acc[1][2*g],   Ah1, Bh[0], Bh[2]);
                mma16816(acc[1][2*g+1], Ah1, Bh[1], Bh[3]);
                mma16816(acc[0][2*g],   Ah0, Bl[0], Bl[2]);
                mma16816(acc[0][2*g+1], Ah0, Bl[1], Bl[3]);
                mma16816(acc[1][2*g],   Ah1, Bl[0], Bl[2]);
                mma16816(acc[1][2*g+1], Ah1, Bl[1], Bl[3]);
                mma16816(acc[0][2*g],   Al0, Bh[0], Bh[2]);
                mma16816(acc[0][2*g+1], Al0, Bh[1], Bh[3]);
                mma16816(acc[1][2*g],   Al1, Bh[0], Bh[2]);
                mma16816(acc[1][2*g+1], Al1, Bh[1], Bh[3]);
            }
        }
        __syncthreads();
    }

    // epilogue
    const int qh = lane >> 2, qr = lane & 3;
    #pragma unroll
    for (int mi=0; mi<2; mi++){
        float p0 = 0.f, p1 = 0.f;
        #pragma unroll
        for (int nf=0; nf<8; nf++){
            int a = warp_n*64 + nf*8 + 2*qr;
            const float* c = acc[mi][nf];
            p0 = fmaf(s_wg[a],   tanhf(c[0] + s_sv[a]),   p0);
            p0 = fmaf(s_wg[a+1], tanhf(c[1] + s_sv[a+1]), p0);
            p1 = fmaf(s_wg[a],   tanhf(c[2] + s_sv[a]),   p1);
            p1 = fmaf(s_wg[a+1], tanhf(c[3] + s_sv[a+1]), p1);
        }
        p0 += __shfl_xor_sync(0xffffffffu, p0, 1);
        p0 += __shfl_xor_sync(0xffffffffu, p0, 2);
        p1 += __shfl_xor_sync(0xffffffffu, p1, 1);
        p1 += __shfl_xor_sync(0xffffffffu, p1, 2);
        if (qr == 0){
            int t = t0 + warp_m*32 + mi*16 + qh;
            if (t < T_)     atomicAdd(&g_e[b*T_ + t],     p0);
            if (t+8 < T_)   atomicAdd(&g_e[b*T_ + t + 8], p1);
        }
    }
}

// ---------------------------------------------------------------------------
// masked scaled softmax
// ---------------------------------------------------------------------------
__global__ void softmax_kernel(const int* __restrict__ len, float* __restrict__ out){
    __shared__ float se[T_];
    __shared__ float red[256];
    int b = blockIdx.x, tid = threadIdx.x;
    int L = len[b];
    for (int t=tid;t<T_;t+=256) se[t] = g_e[b*T_+t];
    __syncthreads();
    float m = -3.4e38f;
    for (int t=tid;t<L;t+=256) m = fmaxf(m, se[t]);
    red[tid]=m; __syncthreads();
    for (int s=128;s>0;s>>=1){ if (tid<s) red[tid]=fmaxf(red[tid],red[tid+s]); __syncthreads(); }
    m = red[0];
    __syncthreads();
    float sum = 0.f;
    for (int t=tid;t<T_;t+=256){
        float v = (t<L) ? expf(2.0f*(se[t]-m)) : 0.f;
        se[t] = v;
        sum += v;
    }
    red[tid]=sum; __syncthreads();
    for (int s=128;s>0;s>>=1){ if (tid<s) red[tid]+=red[tid+s]; __syncthreads(); }
    float inv = 1.0f/red[0];
    for (int t=tid;t<T_;t+=256) out[OUT_W + b*T_ + t] = se[t]*inv;
}

// ---------------------------------------------------------------------------
// ctx = w @ enc, split over t (8 ways) with atomic accumulation
// grid (B, E/256, 8)
// ---------------------------------------------------------------------------
__global__ void ctx_kernel(const float* __restrict__ enc, float* __restrict__ out){
    __shared__ float sw[200];
    int b = blockIdx.x;
    int ec = blockIdx.y*256 + threadIdx.x;
    int tbase = blockIdx.z * 200;
    if (threadIdx.x < 200) sw[threadIdx.x] = out[OUT_W + b*T_ + tbase + threadIdx.x];
    __syncthreads();
    const float* eb = enc + ((size_t)b*T_ + tbase)*E_ + ec;
    float a0=0.f,a1=0.f,a2=0.f,a3=0.f,a4=0.f,a5=0.f,a6=0.f,a7=0.f;
    #pragma unroll 1
    for (int t=0;t<200;t+=8){
        a0 = fmaf(sw[t+0], eb[(size_t)(t+0)*E_], a0);
        a1 = fmaf(sw[t+1], eb[(size_t)(t+1)*E_], a1);
        a2 = fmaf(sw[t+2], eb[(size_t)(t+2)*E_], a2);
        a3 = fmaf(sw[t+3], eb[(size_t)(t+3)*E_], a3);
        a4 = fmaf(sw[t+4], eb[(size_t)(t+4)*E_], a4);
        a5 = fmaf(sw[t+5], eb[(size_t)(t+5)*E_], a5);
        a6 = fmaf(sw[t+6], eb[(size_t)(t+6)*E_], a6);
        a7 = fmaf(sw[t+7], eb[(size_t)(t+7)*E_], a7);
    }
    atomicAdd(&out[OUT_CTX + b*E_ + ec], ((a0+a1)+(a2+a3)) + ((a4+a5)+(a6+a7)));
}

// ---------------------------------------------------------------------------
extern "C" void kernel_launch(void* const* d_in, const int* in_sizes, int n_in,
                              void* d_out, int out_size)
{
    const float* enc      = (const float*)d_in[0];
    const int*   len      = (const int*)  d_in[1];
    const float* dec_z    = (const float*)d_in[2];
    const float* att_prev = (const float*)d_in[3];
    const float* att_h    = (const float*)d_in[4];
    const float* att_c    = (const float*)d_in[5];
    const float* W_enc    = (const float*)d_in[6];
    const float* b_enc    = (const float*)d_in[7];
    const float* W_dec    = (const float*)d_in[8];
    const float* conv_w   = (const float*)d_in[9];
    const float* W_ih     = (const float*)d_in[10];
    const float* W_hh     = (const float*)d_in[11];
    const float* W_g      = (const float*)d_in[12];
    float* out = (float*)d_out;

    cudaFuncSetAttribute(score_kernel,
                         cudaFuncAttributeMaxDynamicSharedMemorySize, SMEM_DYN);

    split_w_kernel<<<A_*E_/4/256, 256>>>(W_enc);
    zero_kernel<<<(B_*T_+1023)/1024, 1024>>>(out);
    conv_kernel<<<dim3(B_, C_), 256>>>(att_prev, conv_w);
    lstm_kernel<<<B_, 512>>>(dec_z, att_h, att_c, b_enc, W_dec, W_ih, W_hh, out);
    score_kernel<<<dim3(MTILES, A_/NT, B_), 256, SMEM_DYN>>>(enc, W_g);
    softmax_kernel<<<B_, 256>>>(len, out);
    ctx_kernel<<<dim3(B_, E_/256, 8), 256>>>(enc, out);
}

// round 5
// speedup vs baseline: 2.9940x; 1.5030x over previous
#include <cuda_runtime.h>
#include <cuda_bf16.h>
#include <cstdint>
#include <math.h>

#define B_   32
#define T_   1600
#define E_   1024
#define D_   1024
#define A_   512
#define C_   10
#define KW   201
#define FILTR 100

// output layout: ctx (B,E), w (B,T), h_new (B,A), c_new (B,A)
#define OUT_CTX 0
#define OUT_W   (B_*E_)
#define OUT_H   (OUT_W + B_*T_)
#define OUT_CN  (OUT_H + B_*A_)

// GEMM tiling
#define MT   128
#define NT   128
#define KC   64
#define NKT  (E_/KC)              // 16
#define MTILES ((T_ + MT - 1)/MT) // 13

// dynamic smem layout (bytes)
#define OFF_A32(st) ((st)*32768)
#define OFF_AH(st)  (65536 + (st)*32768)
#define OFF_AL(st)  (65536 + (st)*32768 + 16384)
#define OFF_B(st)   (131072 + (st)*32768)
#define SMEM_DYN    229376

// -------- scratch --------
__device__ __nv_bfloat16 g_wh[(size_t)A_ * E_];
__device__ __nv_bfloat16 g_wl[(size_t)A_ * E_];
__device__ float g_feat[B_*C_];
__device__ float g_gates[B_*4*A_];   // LSTM pre-activations
__device__ float g_dp[B_*A_];        // dec_proj
__device__ float g_sv[B_*A_];
__device__ float g_e[B_*T_];

static __device__ __forceinline__ float sigmf(float x){ return 1.0f/(1.0f+expf(-x)); }
static __device__ __forceinline__ unsigned smem_u32(const void* p){
    return (unsigned)__cvta_generic_to_shared(p);
}
static __device__ __forceinline__ void cp16(unsigned d, const void* s){
    asm volatile("cp.async.cg.shared.global [%0], [%1], 16;" :: "r"(d), "l"(s));
}
static __device__ __forceinline__ void ldsm4(uint32_t r[4], uint32_t addr){
    asm volatile("ldmatrix.sync.aligned.m8n8.x4.shared.b16 {%0,%1,%2,%3}, [%4];"
                 : "=r"(r[0]), "=r"(r[1]), "=r"(r[2]), "=r"(r[3]) : "r"(addr));
}
static __device__ __forceinline__ void mma16816(float c[4], const uint32_t a[4],
                                                uint32_t b0, uint32_t b1){
    asm volatile("mma.sync.aligned.m16n8k16.row.col.f32.bf16.bf16.f32 "
                 "{%0,%1,%2,%3}, {%4,%5,%6,%7}, {%8,%9}, {%0,%1,%2,%3};"
                 : "+f"(c[0]), "+f"(c[1]), "+f"(c[2]), "+f"(c[3])
                 : "r"(a[0]), "r"(a[1]), "r"(a[2]), "r"(a[3]), "r"(b0), "r"(b1));
}

// ---------------------------------------------------------------------------
__global__ void split_w_kernel(const float* __restrict__ W){
    int i = blockIdx.x*blockDim.x + threadIdx.x;
    float4 v = ((const float4*)W)[i];
    __nv_bfloat162 h0 = __floats2bfloat162_rn(v.x, v.y);
    __nv_bfloat162 h1 = __floats2bfloat162_rn(v.z, v.w);
    float r0 = v.x - __bfloat162float(h0.x);
    float r1 = v.y - __bfloat162float(h0.y);
    float r2 = v.z - __bfloat162float(h1.x);
    float r3 = v.w - __bfloat162float(h1.y);
    __nv_bfloat162 l0 = __floats2bfloat162_rn(r0, r1);
    __nv_bfloat162 l1 = __floats2bfloat162_rn(r2, r3);
    ((__nv_bfloat162*)g_wh)[2*i]   = h0;
    ((__nv_bfloat162*)g_wh)[2*i+1] = h1;
    ((__nv_bfloat162*)g_wl)[2*i]   = l0;
    ((__nv_bfloat162*)g_wl)[2*i+1] = l1;
}

__global__ void zero_kernel(float* __restrict__ out){
    int i = blockIdx.x*blockDim.x + threadIdx.x;
    if (i < B_*T_) g_e[i] = 0.f;
    if (i < B_*E_) out[OUT_CTX + i] = 0.f;
}

// ---------------------------------------------------------------------------
// conv + relu + global max-pool, register sliding window
// ---------------------------------------------------------------------------
__global__ void conv_kernel(const float* __restrict__ ap, const float* __restrict__ cw){
    __shared__ float xp[1808];
    __shared__ float wk[KW+3];
    __shared__ float red[256];
    int b = blockIdx.x, c = blockIdx.y, tid = threadIdx.x;
    for (int i=tid;i<1808;i+=256){
        int t = i - FILTR;
        xp[i] = (t>=0 && t<T_) ? ap[b*T_+t] : 0.f;
    }
    for (int i=tid;i<KW+3;i+=256) wk[i] = (i<KW) ? cw[c*KW + i] : 0.f;
    __syncthreads();
    float m = 0.f;
    #pragma unroll
    for (int p=0;p<2;p++){
        int grp = p*256 + tid;
        if (grp < 400){
            int t0 = grp*4;
            float x0=xp[t0], x1=xp[t0+1], x2=xp[t0+2], x3=xp[t0+3];
            float a0=0.f,a1=0.f,a2=0.f,a3=0.f;
            #pragma unroll 4
            for (int k=0;k<KW;k++){
                float w = wk[k];
                a0 = fmaf(x0, w, a0);
                a1 = fmaf(x1, w, a1);
                a2 = fmaf(x2, w, a2);
                a3 = fmaf(x3, w, a3);
                x0=x1; x1=x2; x2=x3; x3=xp[t0+k+4];
            }
            m = fmaxf(m, fmaxf(fmaxf(a0,a1), fmaxf(a2,a3)));
        }
    }
    red[tid]=m; __syncthreads();
    for (int s=128;s>0;s>>=1){ if (tid<s) red[tid]=fmaxf(red[tid],red[tid+s]); __syncthreads(); }
    if (tid==0) g_feat[b*C_+c] = red[0];
}

// ---------------------------------------------------------------------------
// gates_kernel: grid (B, 20), 512 threads. Block (b,j) -> 128 rows of the
// 2560-row combined space: [0,2048) = LSTM gates, [2048,2560) = dec_proj.
// ---------------------------------------------------------------------------
__global__ __launch_bounds__(512) void gates_kernel(
    const float* __restrict__ dec_z, const float* __restrict__ att_h,
    const float* __restrict__ W_dec, const float* __restrict__ W_ih,
    const float* __restrict__ W_hh)
{
    __shared__ float s_h[A_];
    __shared__ float s_z[D_];
    __shared__ float s_feat[16];
    int b = blockIdx.x, j = blockIdx.y, tid = threadIdx.x;
    int lane = tid & 31, wp = tid >> 5;
    if (tid < C_) s_feat[tid] = g_feat[b*C_+tid];
    s_h[tid] = att_h[b*A_+tid];
    s_z[tid]     = dec_z[b*D_+tid];
    s_z[tid+512] = dec_z[b*D_+tid+512];
    __syncthreads();

    int rbase = j*128 + wp*8;
    #pragma unroll 1
    for (int i=0;i<8;i++){
        int r = rbase + i;
        float acc = 0.f;
        if (r < 4*A_){
            const float* wr = &W_hh[(size_t)r*A_];
            #pragma unroll
            for (int k=0;k<16;k++) acc = fmaf(wr[lane+32*k], s_h[lane+32*k], acc);
            if (lane < C_) acc = fmaf(s_feat[lane], W_ih[r*C_+lane], acc);
            #pragma unroll
            for (int o=16;o>0;o>>=1) acc += __shfl_xor_sync(0xffffffffu, acc, o);
            if (lane==0) g_gates[b*4*A_ + r] = acc;
        } else {
            int rd = r - 4*A_;
            const float* wr = &W_dec[(size_t)rd*D_];
            #pragma unroll
            for (int k=0;k<32;k++) acc = fmaf(wr[lane+32*k], s_z[lane+32*k], acc);
            #pragma unroll
            for (int o=16;o>0;o>>=1) acc += __shfl_xor_sync(0xffffffffu, acc, o);
            if (lane==0) g_dp[b*A_ + rd] = acc;
        }
    }
}

// ---------------------------------------------------------------------------
// lstm_combine: gate nonlinearity + outputs + sv
// ---------------------------------------------------------------------------
__global__ __launch_bounds__(512) void lstm_combine_kernel(
    const float* __restrict__ att_c, const float* __restrict__ b_enc,
    float* __restrict__ out)
{
    int b = blockIdx.x, a = threadIdx.x;
    float ig = g_gates[b*4*A_ + a];
    float fg = g_gates[b*4*A_ + A_ + a];
    float gg = g_gates[b*4*A_ + 2*A_ + a];
    float og = g_gates[b*4*A_ + 3*A_ + a];
    float cn = sigmf(fg)*att_c[b*A_+a] + sigmf(ig)*tanhf(gg);
    float hn = sigmf(og)*tanhf(cn);
    out[OUT_H  + b*A_ + a] = hn;
    out[OUT_CN + b*A_ + a] = cn;
    g_sv[b*A_ + a] = g_dp[b*A_+a] + hn + b_enc[a];
}

// ---------------------------------------------------------------------------
// HMMA score kernel with in-kernel enc hi/lo split.
// ---------------------------------------------------------------------------
__global__ __launch_bounds__(256) void score_kernel(const float* __restrict__ enc,
                                                    const float* __restrict__ Wg)
{
    extern __shared__ char smemc[];
    __shared__ float s_sv[NT];
    __shared__ float s_wg[NT];
    const uint32_t sb0 = smem_u32(smemc);
    const int tid = threadIdx.x;
    const int lane = tid & 31, wid = tid >> 5;
    const int warp_m = wid >> 1, warp_n = wid & 1;
    const int b  = blockIdx.z;
    const int t0 = blockIdx.x * MT;
    const int a0 = blockIdx.y * NT;

    if (tid < NT){ s_sv[tid] = g_sv[b*A_ + a0 + tid]; s_wg[tid] = Wg[a0 + tid]; }

    const float* encb = enc + (size_t)b*T_*E_;
    const __nv_bfloat16* pBh = g_wh + (size_t)a0*E_;
    const __nv_bfloat16* pBl = g_wl + (size_t)a0*E_;

    auto load_stage = [&](int kt){
        const int stA = kt & 1, stB = kt % 3;
        const int kof = kt*KC;
        #pragma unroll
        for (int j=0;j<8;j++){
            int idx = j*256 + tid;
            int row = idx >> 4, ch = idx & 15;
            int trow = t0 + row; if (trow >= T_) trow = T_-1;
            cp16(sb0 + OFF_A32(stA) + row*256 + ch*16,
                 encb + (size_t)trow*E_ + kof + ch*4);
        }
        #pragma unroll
        for (int j=0;j<4;j++){
            int idx = j*256 + tid;
            int row = idx >> 3, ch = idx & 7;
            uint32_t off = (uint32_t)row*128 + (uint32_t)((ch ^ (row & 7)) << 4);
            size_t so = (size_t)row*E_ + kof + ch*8;
            cp16(sb0 + OFF_B(stB) + off,         pBh + so);
            cp16(sb0 + OFF_B(stB) + 16384 + off, pBl + so);
        }
        asm volatile("cp.async.commit_group;" ::: "memory");
    };

    const int lrow = lane & 15, lsel = lane >> 4;
    const int arow0 = warp_m*32 + lrow, arow1 = arow0 + 16;
    const uint32_t aoffr0 = (uint32_t)arow0*128, asx0 = arow0 & 7;
    const uint32_t aoffr1 = (uint32_t)arow1*128, asx1 = arow1 & 7;
    uint32_t boffr[4], bsx[4];
    #pragma unroll
    for (int g=0; g<4; g++){
        int r = warp_n*64 + lrow + g*16;
        boffr[g] = (uint32_t)r*128; bsx[g] = r & 7;
    }

    float acc[2][8][4];
    #pragma unroll
    for (int i=0;i<2;i++)
        #pragma unroll
        for (int j=0;j<8;j++)
            #pragma unroll
            for (int k=0;k<4;k++) acc[i][j][k] = 0.f;

    load_stage(0);
    load_stage(1);

    #pragma unroll 1
    for (int kt = 0; kt < NKT; kt++){
        if (kt == NKT-1) asm volatile("cp.async.wait_group 0;" ::: "memory");
        else             asm volatile("cp.async.wait_group 1;" ::: "memory");
        __syncthreads();

        const int stA = kt & 1, stB = kt % 3;
        {
            const char* a32 = smemc + OFF_A32(stA);
            char* ah = smemc + OFF_AH(stA);
            char* al = smemc + OFF_AL(stA);
            #pragma unroll
            for (int p=0;p<8;p++){
                int f4i = p*256 + tid;
                int row = f4i >> 4, c4 = f4i & 15;
                float4 v = *(const float4*)(a32 + row*256 + c4*16);
                __nv_bfloat162 h0 = __floats2bfloat162_rn(v.x, v.y);
                __nv_bfloat162 h1 = __floats2bfloat162_rn(v.z, v.w);
                float r0 = v.x - __bfloat162float(h0.x);
                float r1 = v.y - __bfloat162float(h0.y);
                float r2 = v.z - __bfloat162float(h1.x);
                float r3 = v.w - __bfloat162float(h1.y);
                __nv_bfloat162 l0 = __floats2bfloat162_rn(r0, r1);
                __nv_bfloat162 l1 = __floats2bfloat162_rn(r2, r3);
                uint32_t boff = (uint32_t)row*128
                              + (uint32_t)(((c4>>1) ^ (row & 7)) << 4)
                              + (uint32_t)((c4 & 1) * 8);
                uint2 hh, ll;
                hh.x = *reinterpret_cast<uint32_t*>(&h0);
                hh.y = *reinterpret_cast<uint32_t*>(&h1);
                ll.x = *reinterpret_cast<uint32_t*>(&l0);
                ll.y = *reinterpret_cast<uint32_t*>(&l1);
                *(uint2*)(ah + boff) = hh;
                *(uint2*)(al + boff) = ll;
            }
        }
        __syncthreads();

        if (kt + 2 < NKT) load_stage(kt+2);

        const uint32_t sAh = sb0 + OFF_AH(stA);
        const uint32_t sAl = sb0 + OFF_AL(stA);
        const uint32_t sBh = sb0 + OFF_B(stB);
        const uint32_t sBl = sBh + 16384;
        #pragma unroll
        for (int k16=0; k16<4; k16++){
            const int ch = k16*2 + lsel;
            uint32_t Ah0[4], Ah1[4], Al0[4], Al1[4];
            uint32_t ao0 = aoffr0 + ((uint32_t)(ch ^ asx0) << 4);
            uint32_t ao1 = aoffr1 + ((uint32_t)(ch ^ asx1) << 4);
            ldsm4(Ah0, sAh + ao0);
            ldsm4(Ah1, sAh + ao1);
            ldsm4(Al0, sAl + ao0);
            ldsm4(Al1, sAl + ao1);
            #pragma unroll
            for (int g=0; g<4; g++){
                uint32_t bo = boffr[g] + ((uint32_t)(ch ^ bsx[g]) << 4);
                uint32_t Bh[4], Bl[4];
                ldsm4(Bh, sBh + bo);
                ldsm4(Bl, sBl + bo);
                mma16816(acc[0][2*g],   Ah0, Bh[0], Bh[2]);
                mma16816(acc[0][2*g+1], Ah0, Bh[1], Bh[3]);
                mma16816(acc[1][2*g],   Ah1, Bh[0], Bh[2]);
                mma16816(acc[1][2*g+1], Ah1, Bh[1], Bh[3]);
                mma16816(acc[0][2*g],   Ah0, Bl[0], Bl[2]);
                mma16816(acc[0][2*g+1], Ah0, Bl[1], Bl[3]);
                mma16816(acc[1][2*g],   Ah1, Bl[0], Bl[2]);
                mma16816(acc[1][2*g+1], Ah1, Bl[1], Bl[3]);
                mma16816(acc[0][2*g],   Al0, Bh[0], Bh[2]);
                mma16816(acc[0][2*g+1], Al0, Bh[1], Bh[3]);
                mma16816(acc[1][2*g],   Al1, Bh[0], Bh[2]);
                mma16816(acc[1][2*g+1], Al1, Bh[1], Bh[3]);
            }
        }
        __syncthreads();
    }

    const int qh = lane >> 2, qr = lane & 3;
    #pragma unroll
    for (int mi=0; mi<2; mi++){
        float p0 = 0.f, p1 = 0.f;
        #pragma unroll
        for (int nf=0; nf<8; nf++){
            int a = warp_n*64 + nf*8 + 2*qr;
            const float* c = acc[mi][nf];
            p0 = fmaf(s_wg[a],   tanhf(c[0] + s_sv[a]),   p0);
            p0 = fmaf(s_wg[a+1], tanhf(c[1] + s_sv[a+1]), p0);
            p1 = fmaf(s_wg[a],   tanhf(c[2] + s_sv[a]),   p1);
            p1 = fmaf(s_wg[a+1], tanhf(c[3] + s_sv[a+1]), p1);
        }
        p0 += __shfl_xor_sync(0xffffffffu, p0, 1);
        p0 += __shfl_xor_sync(0xffffffffu, p0, 2);
        p1 += __shfl_xor_sync(0xffffffffu, p1, 1);
        p1 += __shfl_xor_sync(0xffffffffu, p1, 2);
        if (qr == 0){
            int t = t0 + warp_m*32 + mi*16 + qh;
            if (t < T_)     atomicAdd(&g_e[b*T_ + t],     p0);
            if (t+8 < T_)   atomicAdd(&g_e[b*T_ + t + 8], p1);
        }
    }
}

// ---------------------------------------------------------------------------
__global__ void softmax_kernel(const int* __restrict__ len, float* __restrict__ out){
    __shared__ float se[T_];
    __shared__ float red[256];
    int b = blockIdx.x, tid = threadIdx.x;
    int L = len[b];
    for (int t=tid;t<T_;t+=256) se[t] = g_e[b*T_+t];
    __syncthreads();
    float m = -3.4e38f;
    for (int t=tid;t<L;t+=256) m = fmaxf(m, se[t]);
    red[tid]=m; __syncthreads();
    for (int s=128;s>0;s>>=1){ if (tid<s) red[tid]=fmaxf(red[tid],red[tid+s]); __syncthreads(); }
    m = red[0];
    __syncthreads();
    float sum = 0.f;
    for (int t=tid;t<T_;t+=256){
        float v = (t<L) ? expf(2.0f*(se[t]-m)) : 0.f;
        se[t] = v;
        sum += v;
    }
    red[tid]=sum; __syncthreads();
    for (int s=128;s>0;s>>=1){ if (tid<s) red[tid]+=red[tid+s]; __syncthreads(); }
    float inv = 1.0f/red[0];
    for (int t=tid;t<T_;t+=256) out[OUT_W + b*T_ + t] = se[t]*inv;
}

// ---------------------------------------------------------------------------
__global__ void ctx_kernel(const float* __restrict__ enc, float* __restrict__ out){
    __shared__ float sw[200];
    int b = blockIdx.x;
    int ec = blockIdx.y*256 + threadIdx.x;
    int tbase = blockIdx.z * 200;
    if (threadIdx.x < 200) sw[threadIdx.x] = out[OUT_W + b*T_ + tbase + threadIdx.x];
    __syncthreads();
    const float* eb = enc + ((size_t)b*T_ + tbase)*E_ + ec;
    float a0=0.f,a1=0.f,a2=0.f,a3=0.f,a4=0.f,a5=0.f,a6=0.f,a7=0.f;
    #pragma unroll 1
    for (int t=0;t<200;t+=8){
        a0 = fmaf(sw[t+0], eb[(size_t)(t+0)*E_], a0);
        a1 = fmaf(sw[t+1], eb[(size_t)(t+1)*E_], a1);
        a2 = fmaf(sw[t+2], eb[(size_t)(t+2)*E_], a2);
        a3 = fmaf(sw[t+3], eb[(size_t)(t+3)*E_], a3);
        a4 = fmaf(sw[t+4], eb[(size_t)(t+4)*E_], a4);
        a5 = fmaf(sw[t+5], eb[(size_t)(t+5)*E_], a5);
        a6 = fmaf(sw[t+6], eb[(size_t)(t+6)*E_], a6);
        a7 = fmaf(sw[t+7], eb[(size_t)(t+7)*E_], a7);
    }
    atomicAdd(&out[OUT_CTX + b*E_ + ec], ((a0+a1)+(a2+a3)) + ((a4+a5)+(a6+a7)));
}

// ---------------------------------------------------------------------------
extern "C" void kernel_launch(void* const* d_in, const int* in_sizes, int n_in,
                              void* d_out, int out_size)
{
    const float* enc      = (const float*)d_in[0];
    const int*   len      = (const int*)  d_in[1];
    const float* dec_z    = (const float*)d_in[2];
    const float* att_prev = (const float*)d_in[3];
    const float* att_h    = (const float*)d_in[4];
    const float* att_c    = (const float*)d_in[5];
    const float* W_enc    = (const float*)d_in[6];
    const float* b_enc    = (const float*)d_in[7];
    const float* W_dec    = (const float*)d_in[8];
    const float* conv_w   = (const float*)d_in[9];
    const float* W_ih     = (const float*)d_in[10];
    const float* W_hh     = (const float*)d_in[11];
    const float* W_g      = (const float*)d_in[12];
    float* out = (float*)d_out;

    cudaFuncSetAttribute(score_kernel,
                         cudaFuncAttributeMaxDynamicSharedMemorySize, SMEM_DYN);

    split_w_kernel<<<A_*E_/4/256, 256>>>(W_enc);
    zero_kernel<<<(B_*T_+1023)/1024, 1024>>>(out);
    conv_kernel<<<dim3(B_, C_), 256>>>(att_prev, conv_w);
    gates_kernel<<<dim3(B_, 20), 512>>>(dec_z, att_h, W_dec, W_ih, W_hh);
    lstm_combine_kernel<<<B_, 512>>>(att_c, b_enc, out);
    score_kernel<<<dim3(MTILES, A_/NT, B_), 256, SMEM_DYN>>>(enc, W_g);
    softmax_kernel<<<B_, 256>>>(len, out);
    ctx_kernel<<<dim3(B_, E_/256, 8), 256>>>(enc, out);
}